// round 4
// baseline (speedup 1.0000x reference)
#include <cuda_runtime.h>
#include <cuda_bf16.h>
#include <cstdint>

// y_t = d*y_{t-1} + x_t   per channel, y_{-1} = 0  (so y_0 = x_0)
// x: [BSZ=8, SEQ=4096, CH=1024] fp32, d: [CH] fp32, out same shape as x.
//
// One block per (batch, 32-channel group) column = 256 blocks,
// 256 threads = NSUB(8) t-subtiles x 32 channels, 2 blocks/SM.
// 32 chunks of 128 timesteps; per chunk: register-local serial scan,
// warp-0 cross-subtile affine scan (multiplier d^16) via smem, then
// correction y_i = ylocal_i + d^(i+1)*prefix using a precomputed power
// table (no serial multiply chain on the store path).
//
// Loads are TRIPLE buffered (prefetch distance 2): each chunk's loads get
// ~two chunk bodies (>600 cyc) to complete, covering DRAM latency that the
// distance-1 scheme left exposed (R3 ncu: all pipes < 60% => latency-bound).

#define BSZ    8
#define SEQ    4096
#define CH     1024
#define TSUB   16
#define NSUB   8
#define NTHR   (NSUB * 32)          // 256
#define CHUNK  (TSUB * NSUB)        // 128
#define NCHUNK (SEQ / CHUNK)        // 32
#define CGRPS  (CH / 32)            // 32 channel groups per batch

__global__ __launch_bounds__(NTHR, 2)
void cummulsum_kernel(const float* __restrict__ x,
                      const float* __restrict__ d,
                      float* __restrict__ y)
{
    __shared__ float subAgg[NSUB][32];
    __shared__ float pfx[NSUB][32];

    const int tid  = threadIdx.x;
    const int lane = tid & 31;
    const int s    = tid >> 5;          // subtile index 0..7
    const int b    = blockIdx.x >> 5;   // batch 0..7
    const int cg   = blockIdx.x & 31;   // channel group 0..31
    const int c    = cg * 32 + lane;    // channel

    const float dc = __ldg(d + c);

    // Power table pw[i] = dc^(i+1); computed once, indexed in unrolled loops.
    float pw[TSUB];
    pw[0] = dc;
    #pragma unroll
    for (int i = 1; i < TSUB; i++) pw[i] = pw[i - 1] * dc;
    const float dT = pw[TSUB - 1];      // dc^16

    const size_t colBase = ((size_t)b * SEQ) * CH + (size_t)c;
    const float* xp = x + colBase + (size_t)(s * TSUB) * CH;
    float*       yp = y + colBase + (size_t)(s * TSUB) * CH;

    float carry = 0.0f;   // running per-channel state (meaningful in warp 0)

    float xa[TSUB];       // chunk being processed
    float xb[TSUB];       // chunk k+1 (in flight / arrived)
    float xc[TSUB];       // chunk k+2 (in flight)

    // Prologue: load chunks 0 and 1
    #pragma unroll
    for (int i = 0; i < TSUB; i++) xa[i] = xp[(size_t)i * CH];
    {
        const float* xp1 = xp + (size_t)CHUNK * CH;
        #pragma unroll
        for (int i = 0; i < TSUB; i++) xb[i] = xp1[(size_t)i * CH];
    }

    #pragma unroll 2
    for (int k = 0; k < NCHUNK; k++) {
        // Prefetch chunk k+2: two full chunk bodies to complete.
        const float* xpn = xp + (size_t)(2 * CHUNK) * CH;
        if (k + 2 < NCHUNK) {
            #pragma unroll
            for (int i = 0; i < TSUB; i++) xc[i] = xpn[(size_t)i * CH];
        }

        // Local serial scan in place (zero initial condition)
        #pragma unroll
        for (int i = 1; i < TSUB; i++) xa[i] = fmaf(dc, xa[i - 1], xa[i]);

        subAgg[s][lane] = xa[TSUB - 1];
        __syncthreads();

        if (s == 0) {
            // Cross-subtile affine scan; each lane handles its channel.
            float agg[NSUB];
            #pragma unroll
            for (int j = 0; j < NSUB; j++) agg[j] = subAgg[j][lane];
            float P = carry;
            #pragma unroll
            for (int j = 0; j < NSUB; j++) {
                pfx[j][lane] = P;             // state entering subtile j
                P = fmaf(dT, P, agg[j]);      // advance past subtile j
            }
            carry = P;                         // state entering next chunk
        }
        __syncthreads();

        // Correction + store: y_i = ylocal_i + dc^(i+1) * P (no serial chain)
        const float P = pfx[s][lane];
        #pragma unroll
        for (int i = 0; i < TSUB; i++) {
            yp[(size_t)i * CH] = fmaf(pw[i], P, xa[i]);
        }

        // Rotate buffers (register moves; outer unroll aids renaming)
        #pragma unroll
        for (int i = 0; i < TSUB; i++) { xa[i] = xb[i]; xb[i] = xc[i]; }

        xp += (size_t)CHUNK * CH;
        yp += (size_t)CHUNK * CH;
    }
}

extern "C" void kernel_launch(void* const* d_in, const int* in_sizes, int n_in,
                              void* d_out, int out_size)
{
    const float* x = (const float*)d_in[0];
    const float* d = (const float*)d_in[1];
    float*       y = (float*)d_out;
    (void)in_sizes; (void)n_in; (void)out_size;

    cummulsum_kernel<<<BSZ * CGRPS, NTHR>>>(x, d, y);
}

// round 5
// speedup vs baseline: 1.0753x; 1.0753x over previous
#include <cuda_runtime.h>
#include <cuda_bf16.h>
#include <cstdint>

// y_t = d*y_{t-1} + x_t   per channel, y_{-1} = 0  (so y_0 = x_0)
// x: [BSZ=8, SEQ=4096, CH=1024] fp32, d: [CH] fp32, out same shape as x.
//
// One block per (batch, 32-channel group) column = 256 blocks,
// 256 threads = NSUB(8) t-subtiles x 32 channels, 2 blocks/SM.
// 32 chunks of 128 timesteps per block.
//
// R5 change: NO warp-0 serialization. Every warp redundantly performs the
// 8-step cross-subtile affine scan (multiplier d^16) from smem aggregates
// and maintains its own replicated carry register. One barrier per chunk
// (subAgg double-buffered by chunk parity to kill the WAR hazard), so the
// only cross-warp coupling per chunk is a single bar.sync.

#define BSZ    8
#define SEQ    4096
#define CH     1024
#define TSUB   16
#define NSUB   8
#define NTHR   (NSUB * 32)          // 256
#define CHUNK  (TSUB * NSUB)        // 128
#define NCHUNK (SEQ / CHUNK)        // 32
#define CGRPS  (CH / 32)            // 32 channel groups per batch

__global__ __launch_bounds__(NTHR, 2)
void cummulsum_kernel(const float* __restrict__ x,
                      const float* __restrict__ d,
                      float* __restrict__ y)
{
    __shared__ float subAgg[2][NSUB][32];   // double-buffered by chunk parity

    const int tid  = threadIdx.x;
    const int lane = tid & 31;
    const int s    = tid >> 5;          // subtile index 0..7
    const int b    = blockIdx.x >> 5;   // batch 0..7
    const int cg   = blockIdx.x & 31;   // channel group 0..31
    const int c    = cg * 32 + lane;    // channel

    const float dc = __ldg(d + c);

    // Power table pw[i] = dc^(i+1); indexed in unrolled loops (no serial
    // multiply chain on the store path).
    float pw[TSUB];
    pw[0] = dc;
    #pragma unroll
    for (int i = 1; i < TSUB; i++) pw[i] = pw[i - 1] * dc;
    const float dT = pw[TSUB - 1];      // dc^16

    const size_t colBase = ((size_t)b * SEQ) * CH + (size_t)c;
    const float* xp = x + colBase + (size_t)(s * TSUB) * CH;
    float*       yp = y + colBase + (size_t)(s * TSUB) * CH;

    float carry = 0.0f;   // replicated per-warp running state (identical in all warps)

    float xa[TSUB];
    float xb[TSUB];

    // Prologue: load chunk 0
    #pragma unroll
    for (int i = 0; i < TSUB; i++) xa[i] = xp[(size_t)i * CH];

    #pragma unroll 2
    for (int k = 0; k < NCHUNK; k++) {
        const int p = k & 1;

        // Prefetch next chunk (independent of everything below).
        const float* xpn = xp + (size_t)CHUNK * CH;
        if (k + 1 < NCHUNK) {
            #pragma unroll
            for (int i = 0; i < TSUB; i++) xb[i] = xpn[(size_t)i * CH];
        }

        // Local serial scan in place (zero initial condition)
        #pragma unroll
        for (int i = 1; i < TSUB; i++) xa[i] = fmaf(dc, xa[i - 1], xa[i]);

        subAgg[p][s][lane] = xa[TSUB - 1];
        __syncthreads();

        // Every warp redundantly scans all 8 aggregates; it uses the prefix
        // for its own subtile and updates its private replicated carry.
        float P;                         // state entering subtile s
        {
            float agg[NSUB];
            #pragma unroll
            for (int j = 0; j < NSUB; j++) agg[j] = subAgg[p][j][lane];
            float r = carry;
            P = r;                       // valid if s == 0
            #pragma unroll
            for (int j = 0; j < NSUB; j++) {
                r = fmaf(dT, r, agg[j]); // state entering subtile j+1
                if (j + 1 == s) P = r;
            }
            carry = r;                   // state entering next chunk
        }

        // Correction + store: y_i = ylocal_i + dc^(i+1) * P
        #pragma unroll
        for (int i = 0; i < TSUB; i++) {
            yp[(size_t)i * CH] = fmaf(pw[i], P, xa[i]);
        }

        // Rotate buffers
        #pragma unroll
        for (int i = 0; i < TSUB; i++) xa[i] = xb[i];

        xp += (size_t)CHUNK * CH;
        yp += (size_t)CHUNK * CH;
    }
}

extern "C" void kernel_launch(void* const* d_in, const int* in_sizes, int n_in,
                              void* d_out, int out_size)
{
    const float* x = (const float*)d_in[0];
    const float* d = (const float*)d_in[1];
    float*       y = (float*)d_out;
    (void)in_sizes; (void)n_in; (void)out_size;

    cummulsum_kernel<<<BSZ * CGRPS, NTHR>>>(x, d, y);
}